// round 16
// baseline (speedup 1.0000x reference)
#include <cuda_runtime.h>
#include <cstdint>

#define BN 4
#define WS 512
#define KSEG 256
#define HW (WS*WS)
#define BORDER 32
#define CROPN 802816   // 4 * 448 * 448
#define NBLK 256       // fused kernel grid size (co-resident: spin-barrier safe)

// ---------------- scratch (static device globals; zero-init at load) --------
// g_pbox encoding (all-zero == empty, updates are atomicMax from 0):
//   [0] = WS - minr   [1] = maxr + 1   [2] = WS - minc   [3] = maxc + 1
// All scratch returns to zero by the end of each run (self-cleaning), so every
// graph replay starts from the identical all-zero state.
__device__ int    g_pbox[BN][KSEG][4];
__device__ float  g_proj[BN*HW];           // 4 MB
__device__ int    g_lossi[2];              // integer-exact loss sums (sq, abs)
__device__ unsigned int g_bar0, g_bar1;    // grid barrier arrive counters
__device__ unsigned int g_done;            // final completion ticket

// grid-wide barrier: thread 0 arrives + spins; whole block waits.
__device__ __forceinline__ void grid_bar(volatile unsigned int* ctr) {
    __syncthreads();
    if (threadIdx.x == 0) {
        __threadfence();
        atomicAdd((unsigned int*)ctr, 1u);
        while (*ctr < NBLK) { }
        __threadfence();
    }
    __syncthreads();
}

// ---------------- THE fused kernel ----------------
__global__ void __launch_bounds__(256, 3)
k_all(const int* __restrict__ labels,
      const float* __restrict__ inj,
      const float* __restrict__ trs,
      const float* __restrict__ rot,
      const float* __restrict__ sca,
      const float* __restrict__ gti,
      float* __restrict__ out,
      int mask_off, int write_mask, int write_loss) {

    __shared__ int   s0[KSEG+1], s1[KSEG+1], s2[KSEG+1], s3[KSEG+1];
    __shared__ float s_vals[4][5][8][32];    // phase B staging (20KB)

    // ================= PHASE A: per-instance pixel bounding boxes ==========
    {
        int b  = blockIdx.x >> 6;          // 64 blocks per batch
        int rb = blockIdx.x & 63;          // 8 rows each

        for (int i = threadIdx.x; i <= KSEG; i += 256) {
            s0[i] = 0; s1[i] = 0; s2[i] = 0; s3[i] = 0;
        }
        __syncthreads();

        int row = rb*8 + (threadIdx.x >> 5);      // 8 rows, 32 threads per row
        int c0  = (threadIdx.x & 31) * 16;        // 16 px per thread
        const int base = (b*WS + row)*WS + c0;

        int lv[16];
        const int4* lp = (const int4*)(labels + base);
#pragma unroll
        for (int q = 0; q < 4; q++) {
            int4 t = lp[q];
            lv[q*4+0] = t.x; lv[q*4+1] = t.y; lv[q*4+2] = t.z; lv[q*4+3] = t.w;
        }

        int cur = 0, cmin = 0, cmax = 0;
#pragma unroll
        for (int j = 0; j < 16; j++) {
            int lab = lv[j];
            if (lab != cur) {
                if (cur > 0 && cur <= KSEG) {
                    atomicMax(&s0[cur], WS - row); atomicMax(&s1[cur], row + 1);
                    atomicMax(&s2[cur], WS - cmin); atomicMax(&s3[cur], cmax + 1);
                }
                cur = lab; cmin = c0 + j;
            }
            if (lab) cmax = c0 + j;
        }
        if (cur > 0 && cur <= KSEG) {
            atomicMax(&s0[cur], WS - row); atomicMax(&s1[cur], row + 1);
            atomicMax(&s2[cur], WS - cmin); atomicMax(&s3[cur], cmax + 1);
        }
        __syncthreads();

        for (int l = threadIdx.x + 1; l <= KSEG; l += 256) {
            if (s3[l] > 0) {
                int k = l - 1;
                atomicMax(&g_pbox[b][k][0], s0[l]);
                atomicMax(&g_pbox[b][k][1], s1[l]);
                atomicMax(&g_pbox[b][k][2], s2[l]);
                atomicMax(&g_pbox[b][k][3], s3[l]);
            }
        }
    }

    grid_bar(&g_bar0);

    // ================= PHASE B: stats + transform + inverse + raster =======
    int wwid = threadIdx.x >> 5;
    int lane = threadIdx.x & 31;
    if (wwid < 4) {
        int inst = blockIdx.x * 4 + wwid;
        int b = inst >> 8, k = inst & 255;

        // decode pbox, then reset it to the all-zero empty state
        int p0 = g_pbox[b][k][0], p1 = g_pbox[b][k][1];
        int p2 = g_pbox[b][k][2], p3 = g_pbox[b][k][3];
        __syncwarp();
        if (lane == 0) {
            g_pbox[b][k][0] = 0; g_pbox[b][k][1] = 0;
            g_pbox[b][k][2] = 0; g_pbox[b][k][3] = 0;
        }
        int rmin = WS - p0, rmax = p1 - 1;
        int cmin = WS - p2, cmax = p3 - 1;

        const int kk = k + 1;
        const int lb = b * HW;

        float acc = 0.0f;                    // lanes 0-4: noisy chain
        int icnt = 0, icol = 0, irow = 0;    // exact integer sums

        if (rmax >= 0) {
            int w = cmax - cmin + 1;
            if (w <= 32) {
                // ---------------- fast path ----------------
                const float* srcs[5] = { inj + b*HW, trs + b*2*HW,
                                         trs + b*2*HW + HW, rot + b*HW, sca + b*HW };
                int myc = cmin + lane;
                int ccl = min(myc, cmax);
                bool cok = (myc <= cmax);

                for (int r0 = rmin; r0 <= rmax; r0 += 8) {
                    unsigned int mask[8];
#pragma unroll
                    for (int rr = 0; rr < 8; rr++) {
                        int r  = r0 + rr;
                        int rc = min(r, rmax);
                        int lab = labels[lb + rc*WS + ccl];
                        bool pr = cok && (r <= rmax) && (lab == kk);
                        mask[rr] = __ballot_sync(0xffffffffu, pr);
                    }
#pragma unroll
                    for (int rr = 0; rr < 8; rr++) {
                        int rc  = min(r0 + rr, rmax);
                        int off = rc*WS + ccl;
#pragma unroll
                        for (int L = 0; L < 5; L++)
                            s_vals[wwid][L][rr][lane] = srcs[L][off];
                    }
#pragma unroll
                    for (int rr = 0; rr < 8; rr++) {
                        unsigned int m = mask[rr];
                        int pc = __popc(m);
                        int wsum = __popc(m & 0xAAAAAAAAu)
                                 + (__popc(m & 0xCCCCCCCCu) << 1)
                                 + (__popc(m & 0xF0F0F0F0u) << 2)
                                 + (__popc(m & 0xFF00FF00u) << 3)
                                 + (__popc(m & 0xFFFF0000u) << 4);
                        icnt += pc;
                        icol += pc * cmin + wsum;
                        irow += pc * (r0 + rr);
                    }
                    __syncwarp();
                    if (lane < 5) {
#pragma unroll
                        for (int rr = 0; rr < 8; rr++) {
                            unsigned int m = mask[rr];
                            const float4* vr = (const float4*)&s_vals[wwid][lane][rr][0];
#pragma unroll
                            for (int q = 0; q < 8; q++) {
                                float4 t = vr[q];     // batched LDS.128
                                if ((m >> (q*4+0)) & 1u) acc = __fadd_rn(acc, t.x);
                                if ((m >> (q*4+1)) & 1u) acc = __fadd_rn(acc, t.y);
                                if ((m >> (q*4+2)) & 1u) acc = __fadd_rn(acc, t.z);
                                if ((m >> (q*4+3)) & 1u) acc = __fadd_rn(acc, t.w);
                            }
                        }
                    }
                    __syncwarp();
                }
            } else {
                // ---------------- fallback (bit-identical order) -------------
                if (lane < 5) {
                    const float* src;
                    switch (lane) {
                        case 0:  src = inj + b*HW;           break;
                        case 1:  src = trs + b*2*HW;         break;
                        case 2:  src = trs + b*2*HW + HW;    break;
                        case 3:  src = rot + b*HW;           break;
                        default: src = sca + b*HW;           break;
                    }
                    for (int r = rmin; r <= rmax; r++) {
                        const int*   lrow = labels + lb + r*WS;
                        const float* vrow = src + r*WS;
                        for (int cb = cmin; cb <= cmax; cb += 32) {
#pragma unroll
                            for (int j = 0; j < 32; j++) {
                                int c  = cb + j;
                                int cc = min(c, cmax);
                                int   lab = lrow[cc];
                                float v   = vrow[cc];
                                if (c <= cmax && lab == kk)
                                    acc = __fadd_rn(acc, v);
                            }
                        }
                    }
                } else {
                    int n = (rmax - rmin + 1) * w;
#pragma unroll 2
                    for (int i = lane - 5; i < n; i += 27) {
                        int r = rmin + i / w;
                        int c = cmin + i % w;
                        if (labels[lb + r*WS + c] == kk) { icnt++; icol += c; irow += r; }
                    }
                    icnt = __reduce_add_sync(0xFFFFFFE0u, icnt);
                    icol = __reduce_add_sync(0xFFFFFFE0u, icol);
                    irow = __reduce_add_sync(0xFFFFFFE0u, irow);
                }
            }
        }

        // gather stats to every lane (warp converged here)
        float v_inj = __shfl_sync(0xffffffffu, acc, 0);
        float v_t0  = __shfl_sync(0xffffffffu, acc, 1);
        float v_t1  = __shfl_sync(0xffffffffu, acc, 2);
        float v_r   = __shfl_sync(0xffffffffu, acc, 3);
        float v_s   = __shfl_sync(0xffffffffu, acc, 4);
        float v_cnt = (float)__shfl_sync(0xffffffffu, icnt, 5);
        float v_col = (float)__shfl_sync(0xffffffffu, icol, 5);
        float v_row = (float)__shfl_sync(0xffffffffu, irow, 5);

        // ---- transform + inverse (uniform across warp; frozen numerics) ----
        float safe = fmaxf(v_cnt, 1.0f);
        float bx  = __fdiv_rn(v_col, safe);
        float by  = __fdiv_rn(v_row, safe);
        float rem = __fdiv_rn(v_inj, safe);
        float ti  = __fdiv_rn(v_t0,  safe);
        float tj  = __fdiv_rn(v_t1,  safe);
        float r   = __fdiv_rn(v_r,   safe);
        float s   = __fdiv_rn(v_s,   safe);

        if ((v_cnt > 0.f) && (rem < 0.5f)) {
            // sin/cos: correctly rounded via double (matches glibc sinf/cosf)
            float c  = (float)cos((double)r);
            float sn = (float)sin((double)r);

            // H = T @ Bm_ @ S @ R @ Bm via fmuladd dot chains
            float bxn = __fdiv_rn(__fsub_rn(256.0f, bx), 256.0f);
            float byn = __fdiv_rn(__fsub_rn(256.0f, by), 256.0f);
            float a   = __fadd_rn(1.0f, s);
            float A   = __fmul_rn(a, c);
            float Bv  = __fmul_rn(a, sn);
            float tx0 = __fsub_rn(ti, bxn);
            float ty0 = __fsub_rn(tj, byn);
            float h02 = __fadd_rn(__fmaf_rn(-Bv, byn, __fmul_rn(A, bxn)), tx0);
            float h12 = __fadd_rn(__fmaf_rn( A, byn, __fmul_rn(Bv, bxn)), ty0);

            // LU (reciprocal scal + fma ger)
            float rA  = __fdiv_rn(1.0f, A);
            float l10 = __fmul_rn(Bv, rA);
            float u11 = __fmaf_rn(l10, Bv, A);
            float u12 = __fmaf_rn(l10, -h02, h12);

            // triangular solves, diagonal pre-inverted
            float rU  = __fdiv_rn(1.0f, u11);
            float i10 = __fmul_rn(-l10, rU);
            float i00 = __fmul_rn(__fmaf_rn(Bv, i10, 1.0f), rA);
            float i11 = rU;
            float i01 = __fmul_rn(__fmul_rn(Bv, rU), rA);
            float i12 = __fmul_rn(-u12, rU);
            float i02 = __fmul_rn(__fsub_rn(__fmul_rn(Bv, i12), h02), rA);

            // output bbox: forward image (double) of src pixel bbox, pad 3 px
            double dA = (double)A, dB = (double)Bv;
            double us0 = ((double)cmin - 0.5) / 255.5 - 1.0;
            double us1 = ((double)cmax + 0.5) / 255.5 - 1.0;
            double vs0 = ((double)rmin - 0.5) / 255.5 - 1.0;
            double vs1 = ((double)rmax + 0.5) / 255.5 - 1.0;

            double xmn = 1e30, xmx = -1e30, ymn = 1e30, ymx = -1e30;
#pragma unroll
            for (int ci = 0; ci < 4; ci++) {
                double us = (ci & 1) ? us1 : us0;
                double vs = (ci & 2) ? vs1 : vs0;
                double uo = dA*us - dB*vs + (double)h02;
                double vo = dB*us + dA*vs + (double)h12;
                double xo = (uo + 1.0) * 255.5;
                double yo = (vo + 1.0) * 255.5;
                xmn = fmin(xmn, xo); xmx = fmax(xmx, xo);
                ymn = fmin(ymn, yo); ymx = fmax(ymx, yo);
            }
            int x0 = max(0,    (int)floor(xmn) - 3);
            int x1 = min(WS-1, (int)ceil (xmx) + 3);
            int y0 = max(0,    (int)floor(ymn) - 3);
            int y1 = min(WS-1, (int)ceil (ymx) + 3);

            int w2 = x1 - x0 + 1, h2 = y1 - y0 + 1;
            if (w2 > 0 && h2 > 0) {
                int n = w2 * h2;
                const float STEP = 2.0f / 511.0f;
#pragma unroll 4
                for (int i = lane; i < n; i += 32) {
                    int x = x0 + i % w2;
                    int y = y0 + i / w2;
                    float gx = __fmaf_rn((float)x, STEP, -1.0f);
                    float gy = __fmaf_rn((float)y, STEP, -1.0f);
                    float u = __fadd_rn(__fmaf_rn(i00, gx, __fmul_rn(i01, gy)), i02);
                    float v = __fadd_rn(__fmaf_rn(i10, gx, __fmul_rn(i11, gy)), i12);
                    int ix = __float2int_rn(__fmul_rn(__fadd_rn(u, 1.0f), 255.5f));
                    int iy = __float2int_rn(__fmul_rn(__fadd_rn(v, 1.0f), 255.5f));
                    if (ix >= 0 && ix < WS && iy >= 0 && iy < WS) {
                        if (labels[lb + iy*WS + ix] == kk)
                            atomicAdd(&g_proj[lb + y*WS + x], 1.0f);
                    }
                }
            }
        }
    }

    grid_bar(&g_bar1);

    // ================= PHASE C: mask + loss + cleanup ======================
    {
        int t = blockIdx.x * blockDim.x + threadIdx.x;   // 16 px per thread
        int f4 = t * 4;
        int pix = t * 16;

        float4* projv = (float4*)g_proj;
        const float4* gtiv = (const float4*)gti;

        int rem = pix & (HW - 1);
        int y  = rem >> 9;
        int xb = rem & (WS - 1);
        int in_rows = (y >= BORDER) && (y < WS - BORDER);

        float4 p[4], g[4];
#pragma unroll
        for (int q = 0; q < 4; q++) p[q] = projv[f4 + q];
        if (in_rows) {
#pragma unroll
            for (int q = 0; q < 4; q++) g[q] = gtiv[f4 + q];
        } else {
#pragma unroll
            for (int q = 0; q < 4; q++) g[q] = make_float4(0.f,0.f,0.f,0.f);
        }

        // re-zero proj for the next graph replay
        float4 z = make_float4(0.f, 0.f, 0.f, 0.f);
#pragma unroll
        for (int q = 0; q < 4; q++) projv[f4 + q] = z;

        if (write_mask) {
#pragma unroll
            for (int q = 0; q < 4; q++) {
                float* o = out + mask_off + pix + q*4;
                o[0] = (p[q].x != 0.f) ? 1.f : 0.f;
                o[1] = (p[q].y != 0.f) ? 1.f : 0.f;
                o[2] = (p[q].z != 0.f) ? 1.f : 0.f;
                o[3] = (p[q].w != 0.f) ? 1.f : 0.f;
            }
        }

        int isq = 0, iab = 0;
        if (in_rows) {
#pragma unroll
            for (int q = 0; q < 4; q++) {
                float pv[4] = {p[q].x, p[q].y, p[q].z, p[q].w};
                float gv[4] = {g[q].x, g[q].y, g[q].z, g[q].w};
#pragma unroll
                for (int j = 0; j < 4; j++) {
                    int x = xb + q*4 + j;
                    if (x >= BORDER && x < WS - BORDER) {
                        float d = __fsub_rn(pv[j], gv[j]);   // integer-valued
                        int di = (int)d;
                        isq += di * di;
                        iab += (di < 0) ? -di : di;
                    }
                }
            }
        }
        isq = __reduce_add_sync(0xffffffffu, isq);
        iab = __reduce_add_sync(0xffffffffu, iab);
        if ((threadIdx.x & 31) == 0) {
            if (isq) atomicAdd(&g_lossi[0], isq);
            if (iab) atomicAdd(&g_lossi[1], iab);
        }

        // last-block-done ticket -> loss write + full scratch reset
        __shared__ int s_last;
        __threadfence();
        __syncthreads();
        if (threadIdx.x == 0) {
            unsigned int done = atomicAdd(&g_done, 1u);
            s_last = (done == (unsigned)(gridDim.x - 1));
        }
        __syncthreads();
        if (s_last && threadIdx.x == 0) {
            if (write_loss) {
                float m1 = __fdiv_rn((float)g_lossi[0], (float)CROPN);
                float m2 = __fdiv_rn((float)g_lossi[1], (float)CROPN);
                out[0] = __fadd_rn(m1, m2);
            }
            // restore all-zero state (all blocks are past both barriers here)
            g_lossi[0] = 0; g_lossi[1] = 0;
            g_bar0 = 0u; g_bar1 = 0u;
            g_done = 0u;
        }
    }
}

// ---------------- launch ----------------
extern "C" void kernel_launch(void* const* d_in, const int* in_sizes, int n_in,
                              void* d_out, int out_size) {
    // metadata order: rgb, mod, gti, seg_inj, trs, rot, sca, labels
    const float* gti    = (const float*)d_in[2];
    const float* inj    = (const float*)d_in[3];
    const float* trs    = (const float*)d_in[4];
    const float* rot    = (const float*)d_in[5];
    const float* sca    = (const float*)d_in[6];
    const int*   labels = (const int*)  d_in[7];
    float* out = (float*)d_out;

    int write_mask = 0, mask_off = 0, write_loss = 1;
    if (out_size >= BN*HW + 1)      { write_mask = 1; mask_off = 1; }
    else if (out_size == BN*HW)     { write_mask = 1; mask_off = 0; write_loss = 0; }

    k_all<<<NBLK, 256>>>(labels, inj, trs, rot, sca, gti, out,
                         mask_off, write_mask, write_loss);
}

// round 17
// speedup vs baseline: 1.1873x; 1.1873x over previous
#include <cuda_runtime.h>
#include <cstdint>

#define BN 4
#define WS 512
#define KSEG 256
#define HW (WS*WS)
#define BORDER 32
#define CROPN 802816   // 4 * 448 * 448

// ---------------- scratch (static device globals; zero-init at load) --------
// g_pbox encoding (all-zero == empty, updates are atomicMax from 0):
//   [0] = WS - minr   [1] = maxr + 1   [2] = WS - minc   [3] = maxc + 1
// Every kernel restores its scratch to zero after use, so each graph replay
// starts from the identical all-zero state.
__device__ int    g_pbox[BN][KSEG][4];
__device__ float  g_proj[BN*HW];           // 4 MB
__device__ int    g_lossi[2];              // integer-exact loss sums (sq, abs)
__device__ unsigned int g_done;            // k_final completion ticket

// ---------------- kernel 1: per-instance pixel bounding boxes ---------------
// 256 blocks x 256 threads (r13 config — measured faster than 128 blocks).
__global__ void k_pbox(const int* __restrict__ labels) {
    __shared__ int s0[KSEG+1], s1[KSEG+1], s2[KSEG+1], s3[KSEG+1];
    int b  = blockIdx.x >> 6;          // 64 blocks per batch
    int rb = blockIdx.x & 63;          // 8 rows each

    for (int i = threadIdx.x; i <= KSEG; i += 256) {
        s0[i] = 0; s1[i] = 0; s2[i] = 0; s3[i] = 0;
    }
    __syncthreads();

    int row = rb*8 + (threadIdx.x >> 5);      // 8 rows, 32 threads per row
    int c0  = (threadIdx.x & 31) * 16;        // 16 px per thread
    const int base = (b*WS + row)*WS + c0;

    int lv[16];
    const int4* lp = (const int4*)(labels + base);
#pragma unroll
    for (int q = 0; q < 4; q++) {
        int4 t = lp[q];
        lv[q*4+0] = t.x; lv[q*4+1] = t.y; lv[q*4+2] = t.z; lv[q*4+3] = t.w;
    }

    int cur = 0, cmin = 0, cmax = 0;
#pragma unroll
    for (int j = 0; j < 16; j++) {
        int lab = lv[j];
        if (lab != cur) {
            if (cur > 0 && cur <= KSEG) {
                atomicMax(&s0[cur], WS - row); atomicMax(&s1[cur], row + 1);
                atomicMax(&s2[cur], WS - cmin); atomicMax(&s3[cur], cmax + 1);
            }
            cur = lab; cmin = c0 + j;
        }
        if (lab) cmax = c0 + j;
    }
    if (cur > 0 && cur <= KSEG) {
        atomicMax(&s0[cur], WS - row); atomicMax(&s1[cur], row + 1);
        atomicMax(&s2[cur], WS - cmin); atomicMax(&s3[cur], cmax + 1);
    }
    __syncthreads();

    for (int l = threadIdx.x + 1; l <= KSEG; l += 256) {
        if (s3[l] > 0) {
            int k = l - 1;
            atomicMax(&g_pbox[b][k][0], s0[l]);
            atomicMax(&g_pbox[b][k][1], s1[l]);
            atomicMax(&g_pbox[b][k][2], s2[l]);
            atomicMax(&g_pbox[b][k][3], s3[l]);
        }
    }
}

// ---------------- kernel 2: stats + transform + inverse + raster (fused) ----
// One warp per (b,k). Fast path (bbox width <= 32): ballot masks + shared
// staging; the order-sensitive chains use BRANCH-FREE select-adds:
//   t = fadd(acc, v); acc = bit ? t : acc;    (FADD+SEL, no BSSY/BSYNC)
// — bit-identical to the conditional add (selected value IS the cond result).
__global__ void k_statraster(const int* __restrict__ labels,
                             const float* __restrict__ inj,
                             const float* __restrict__ trs,
                             const float* __restrict__ rot,
                             const float* __restrict__ sca) {
    __shared__ float s_vals[4][5][8][32];    // [warp][array][row][col] 20KB
    int wwid = threadIdx.x >> 5;
    int inst = blockIdx.x * 4 + wwid;
    int lane = threadIdx.x & 31;
    int b = inst >> 8, k = inst & 255;

    // decode pbox, then reset it to the all-zero empty state
    int p0 = g_pbox[b][k][0], p1 = g_pbox[b][k][1];
    int p2 = g_pbox[b][k][2], p3 = g_pbox[b][k][3];
    __syncwarp();
    if (lane == 0) {
        g_pbox[b][k][0] = 0; g_pbox[b][k][1] = 0;
        g_pbox[b][k][2] = 0; g_pbox[b][k][3] = 0;
    }
    int rmin = WS - p0, rmax = p1 - 1;
    int cmin = WS - p2, cmax = p3 - 1;

    const int kk = k + 1;
    const int lb = b * HW;

    float acc = 0.0f;                    // lanes 0-4: noisy chain
    int icnt = 0, icol = 0, irow = 0;    // exact integer sums

    if (rmax >= 0) {
        int w = cmax - cmin + 1;
        if (w <= 32) {
            // ---------------- fast path ----------------
            const float* srcs[5] = { inj + b*HW, trs + b*2*HW,
                                     trs + b*2*HW + HW, rot + b*HW, sca + b*HW };
            int myc = cmin + lane;
            int ccl = min(myc, cmax);
            bool cok = (myc <= cmax);

            for (int r0 = rmin; r0 <= rmax; r0 += 8) {
                unsigned int mask[8];
#pragma unroll
                for (int rr = 0; rr < 8; rr++) {
                    int r  = r0 + rr;
                    int rc = min(r, rmax);
                    int lab = labels[lb + rc*WS + ccl];
                    bool pr = cok && (r <= rmax) && (lab == kk);
                    mask[rr] = __ballot_sync(0xffffffffu, pr);
                }
#pragma unroll
                for (int rr = 0; rr < 8; rr++) {
                    int rc  = min(r0 + rr, rmax);
                    int off = rc*WS + ccl;
#pragma unroll
                    for (int L = 0; L < 5; L++)
                        s_vals[wwid][L][rr][lane] = srcs[L][off];
                }
#pragma unroll
                for (int rr = 0; rr < 8; rr++) {
                    unsigned int m = mask[rr];
                    int pc = __popc(m);
                    int wsum = __popc(m & 0xAAAAAAAAu)
                             + (__popc(m & 0xCCCCCCCCu) << 1)
                             + (__popc(m & 0xF0F0F0F0u) << 2)
                             + (__popc(m & 0xFF00FF00u) << 3)
                             + (__popc(m & 0xFFFF0000u) << 4);
                    icnt += pc;
                    icol += pc * cmin + wsum;
                    irow += pc * (r0 + rr);
                }
                __syncwarp();
                if (lane < 5) {
#pragma unroll
                    for (int rr = 0; rr < 8; rr++) {
                        unsigned int m = mask[rr];
                        const float4* vr = (const float4*)&s_vals[wwid][lane][rr][0];
#pragma unroll
                        for (int q = 0; q < 8; q++) {
                            float4 t = vr[q];     // batched LDS.128
                            float a0 = __fadd_rn(acc, t.x);
                            acc = ((m >> (q*4+0)) & 1u) ? a0 : acc;
                            float a1 = __fadd_rn(acc, t.y);
                            acc = ((m >> (q*4+1)) & 1u) ? a1 : acc;
                            float a2 = __fadd_rn(acc, t.z);
                            acc = ((m >> (q*4+2)) & 1u) ? a2 : acc;
                            float a3 = __fadd_rn(acc, t.w);
                            acc = ((m >> (q*4+3)) & 1u) ? a3 : acc;
                        }
                    }
                }
                __syncwarp();
            }
        } else {
            // ---------------- fallback (bit-identical order) ----------------
            if (lane < 5) {
                const float* src;
                switch (lane) {
                    case 0:  src = inj + b*HW;           break;
                    case 1:  src = trs + b*2*HW;         break;
                    case 2:  src = trs + b*2*HW + HW;    break;
                    case 3:  src = rot + b*HW;           break;
                    default: src = sca + b*HW;           break;
                }
                for (int r = rmin; r <= rmax; r++) {
                    const int*   lrow = labels + lb + r*WS;
                    const float* vrow = src + r*WS;
                    for (int cb = cmin; cb <= cmax; cb += 32) {
#pragma unroll
                        for (int j = 0; j < 32; j++) {
                            int c  = cb + j;
                            int cc = min(c, cmax);
                            int   lab = lrow[cc];
                            float v   = vrow[cc];
                            float t = __fadd_rn(acc, v);
                            acc = (c <= cmax && lab == kk) ? t : acc;
                        }
                    }
                }
            } else {
                int n = (rmax - rmin + 1) * w;
#pragma unroll 2
                for (int i = lane - 5; i < n; i += 27) {
                    int r = rmin + i / w;
                    int c = cmin + i % w;
                    if (labels[lb + r*WS + c] == kk) { icnt++; icol += c; irow += r; }
                }
                icnt = __reduce_add_sync(0xFFFFFFE0u, icnt);
                icol = __reduce_add_sync(0xFFFFFFE0u, icol);
                irow = __reduce_add_sync(0xFFFFFFE0u, irow);
            }
        }
    }

    // gather stats to every lane (warp converged here)
    float v_inj = __shfl_sync(0xffffffffu, acc, 0);
    float v_t0  = __shfl_sync(0xffffffffu, acc, 1);
    float v_t1  = __shfl_sync(0xffffffffu, acc, 2);
    float v_r   = __shfl_sync(0xffffffffu, acc, 3);
    float v_s   = __shfl_sync(0xffffffffu, acc, 4);
    float v_cnt = (float)__shfl_sync(0xffffffffu, icnt, 5);
    float v_col = (float)__shfl_sync(0xffffffffu, icol, 5);
    float v_row = (float)__shfl_sync(0xffffffffu, irow, 5);

    // ---- transform + inverse (uniform across warp; frozen numerics) ----
    float safe = fmaxf(v_cnt, 1.0f);
    float bx  = __fdiv_rn(v_col, safe);
    float by  = __fdiv_rn(v_row, safe);
    float rem = __fdiv_rn(v_inj, safe);
    float ti  = __fdiv_rn(v_t0,  safe);
    float tj  = __fdiv_rn(v_t1,  safe);
    float r   = __fdiv_rn(v_r,   safe);
    float s   = __fdiv_rn(v_s,   safe);

    if (!((v_cnt > 0.f) && (rem < 0.5f))) return;   // invalid: warp exits

    // sin/cos: correctly rounded via double (matches glibc sinf/cosf)
    float c  = (float)cos((double)r);
    float sn = (float)sin((double)r);

    // H = T @ Bm_ @ S @ R @ Bm via fmuladd dot chains (XLA DotOpEmitter)
    float bxn = __fdiv_rn(__fsub_rn(256.0f, bx), 256.0f);
    float byn = __fdiv_rn(__fsub_rn(256.0f, by), 256.0f);
    float a   = __fadd_rn(1.0f, s);
    float A   = __fmul_rn(a, c);
    float Bv  = __fmul_rn(a, sn);
    float tx0 = __fsub_rn(ti, bxn);
    float ty0 = __fsub_rn(tj, byn);
    float h02 = __fadd_rn(__fmaf_rn(-Bv, byn, __fmul_rn(A, bxn)), tx0);
    float h12 = __fadd_rn(__fmaf_rn( A, byn, __fmul_rn(Bv, bxn)), ty0);

    // LU (reciprocal scal + fma ger)
    float rA  = __fdiv_rn(1.0f, A);
    float l10 = __fmul_rn(Bv, rA);
    float u11 = __fmaf_rn(l10, Bv, A);
    float u12 = __fmaf_rn(l10, -h02, h12);

    // triangular solves, diagonal pre-inverted
    float rU  = __fdiv_rn(1.0f, u11);
    float i10 = __fmul_rn(-l10, rU);
    float i00 = __fmul_rn(__fmaf_rn(Bv, i10, 1.0f), rA);
    float i11 = rU;
    float i01 = __fmul_rn(__fmul_rn(Bv, rU), rA);
    float i12 = __fmul_rn(-u12, rU);
    float i02 = __fmul_rn(__fsub_rn(__fmul_rn(Bv, i12), h02), rA);

    // output bbox: forward image (double) of src pixel bbox, pad 3 px
    double dA = (double)A, dB = (double)Bv;
    double us0 = ((double)cmin - 0.5) / 255.5 - 1.0;
    double us1 = ((double)cmax + 0.5) / 255.5 - 1.0;
    double vs0 = ((double)rmin - 0.5) / 255.5 - 1.0;
    double vs1 = ((double)rmax + 0.5) / 255.5 - 1.0;

    double xmn = 1e30, xmx = -1e30, ymn = 1e30, ymx = -1e30;
#pragma unroll
    for (int ci = 0; ci < 4; ci++) {
        double us = (ci & 1) ? us1 : us0;
        double vs = (ci & 2) ? vs1 : vs0;
        double uo = dA*us - dB*vs + (double)h02;
        double vo = dB*us + dA*vs + (double)h12;
        double xo = (uo + 1.0) * 255.5;
        double yo = (vo + 1.0) * 255.5;
        xmn = fmin(xmn, xo); xmx = fmax(xmx, xo);
        ymn = fmin(ymn, yo); ymx = fmax(ymx, yo);
    }
    int x0 = max(0,    (int)floor(xmn) - 3);
    int x1 = min(WS-1, (int)ceil (xmx) + 3);
    int y0 = max(0,    (int)floor(ymn) - 3);
    int y1 = min(WS-1, (int)ceil (ymx) + 3);

    int w2 = x1 - x0 + 1, h2 = y1 - y0 + 1;
    if (w2 <= 0 || h2 <= 0) return;
    int n = w2 * h2;

    // ---- fused raster (frozen numerics; unroll 8 for load batching) ----
    const float STEP = 2.0f / 511.0f;
#pragma unroll 8
    for (int i = lane; i < n; i += 32) {
        int x = x0 + i % w2;
        int y = y0 + i / w2;
        float gx = __fmaf_rn((float)x, STEP, -1.0f);
        float gy = __fmaf_rn((float)y, STEP, -1.0f);
        float u = __fadd_rn(__fmaf_rn(i00, gx, __fmul_rn(i01, gy)), i02);
        float v = __fadd_rn(__fmaf_rn(i10, gx, __fmul_rn(i11, gy)), i12);
        int ix = __float2int_rn(__fmul_rn(__fadd_rn(u, 1.0f), 255.5f));
        int iy = __float2int_rn(__fmul_rn(__fadd_rn(v, 1.0f), 255.5f));
        if (ix >= 0 && ix < WS && iy >= 0 && iy < WS) {
            if (labels[lb + iy*WS + ix] == kk)
                atomicAdd(&g_proj[lb + y*WS + x], 1.0f);
        }
    }
}

// ---------------- kernel 3: mask + loss + loss write + proj re-zero ---------
__global__ void k_final(const float* __restrict__ gti, float* __restrict__ out,
                        int mask_off, int write_mask, int write_loss) {
    int t = blockIdx.x * blockDim.x + threadIdx.x;   // 16 px per thread
    int f4 = t * 4;
    int pix = t * 16;

    float4* projv = (float4*)g_proj;
    const float4* gtiv = (const float4*)gti;

    int rem = pix & (HW - 1);
    int y  = rem >> 9;
    int xb = rem & (WS - 1);
    int in_rows = (y >= BORDER) && (y < WS - BORDER);

    float4 p[4], g[4];
#pragma unroll
    for (int q = 0; q < 4; q++) p[q] = projv[f4 + q];
    if (in_rows) {
#pragma unroll
        for (int q = 0; q < 4; q++) g[q] = gtiv[f4 + q];
    } else {
#pragma unroll
        for (int q = 0; q < 4; q++) g[q] = make_float4(0.f,0.f,0.f,0.f);
    }

    // re-zero proj for the next graph replay
    float4 z = make_float4(0.f, 0.f, 0.f, 0.f);
#pragma unroll
    for (int q = 0; q < 4; q++) projv[f4 + q] = z;

    if (write_mask) {
#pragma unroll
        for (int q = 0; q < 4; q++) {
            float* o = out + mask_off + pix + q*4;
            o[0] = (p[q].x != 0.f) ? 1.f : 0.f;
            o[1] = (p[q].y != 0.f) ? 1.f : 0.f;
            o[2] = (p[q].z != 0.f) ? 1.f : 0.f;
            o[3] = (p[q].w != 0.f) ? 1.f : 0.f;
        }
    }

    int isq = 0, iab = 0;
    if (in_rows) {
#pragma unroll
        for (int q = 0; q < 4; q++) {
            float pv[4] = {p[q].x, p[q].y, p[q].z, p[q].w};
            float gv[4] = {g[q].x, g[q].y, g[q].z, g[q].w};
#pragma unroll
            for (int j = 0; j < 4; j++) {
                int x = xb + q*4 + j;
                if (x >= BORDER && x < WS - BORDER) {
                    float d = __fsub_rn(pv[j], gv[j]);   // integer-valued
                    int di = (int)d;
                    isq += di * di;
                    iab += (di < 0) ? -di : di;
                }
            }
        }
    }
    isq = __reduce_add_sync(0xffffffffu, isq);
    iab = __reduce_add_sync(0xffffffffu, iab);
    if ((threadIdx.x & 31) == 0) {
        if (isq) atomicAdd(&g_lossi[0], isq);
        if (iab) atomicAdd(&g_lossi[1], iab);
    }

    // last-block-done ticket -> write loss scalar, reset counters
    __shared__ int s_last;
    __threadfence();
    __syncthreads();
    if (threadIdx.x == 0) {
        unsigned int done = atomicAdd(&g_done, 1u);
        s_last = (done == gridDim.x - 1u);
    }
    __syncthreads();
    if (s_last && threadIdx.x == 0) {
        if (write_loss) {
            float m1 = __fdiv_rn((float)g_lossi[0], (float)CROPN);
            float m2 = __fdiv_rn((float)g_lossi[1], (float)CROPN);
            out[0] = __fadd_rn(m1, m2);
        }
        g_lossi[0] = 0; g_lossi[1] = 0;   // restore zero state
        g_done = 0u;
    }
}

// ---------------- launch ----------------
extern "C" void kernel_launch(void* const* d_in, const int* in_sizes, int n_in,
                              void* d_out, int out_size) {
    // metadata order: rgb, mod, gti, seg_inj, trs, rot, sca, labels
    const float* gti    = (const float*)d_in[2];
    const float* inj    = (const float*)d_in[3];
    const float* trs    = (const float*)d_in[4];
    const float* rot    = (const float*)d_in[5];
    const float* sca    = (const float*)d_in[6];
    const int*   labels = (const int*)  d_in[7];
    float* out = (float*)d_out;

    int write_mask = 0, mask_off = 0, write_loss = 1;
    if (out_size >= BN*HW + 1)      { write_mask = 1; mask_off = 1; }
    else if (out_size == BN*HW)     { write_mask = 1; mask_off = 0; write_loss = 0; }

    k_pbox       <<<BN*64, 256>>>(labels);
    k_statraster <<<BN*KSEG/4, 128>>>(labels, inj, trs, rot, sca);
    k_final      <<<BN*HW/16/256, 256>>>(gti, out, mask_off, write_mask, write_loss);
}